// round 1
// baseline (speedup 1.0000x reference)
#include <cuda_runtime.h>
#include <math.h>

#define TTOK 8192
#define DDIM 1024
#define HDIM 1408
#define NE   8

// ---- device scratch (static allocations only; no cudaMalloc anywhere) ----
__device__ int    g_ecount[NE];
__device__ int    g_etok[NE][TTOK];
__device__ float  g_ew[NE][TTOK];
__device__ double g_usage[NE];
__device__ float  g_hbuf[NE][TTOK][HDIM];   // ~369 MB static scratch

// ============================================================
// K0: zero output accumulator + counters
// ============================================================
__global__ void k_init(float* __restrict__ out) {
    int i = blockIdx.x * 256 + threadIdx.x;
    if (i < TTOK * DDIM) out[i] = 0.f;
    if (i < NE) { g_ecount[i] = 0; g_usage[i] = 0.0; }
}

// ============================================================
// K1: router — warp per token. logits = x_t . Wr, softmax, top-2,
// scatter into per-expert buckets, usage accumulation (double).
// ============================================================
__global__ void __launch_bounds__(128) k_router(const float* __restrict__ x,
                                                const float* __restrict__ Wr) {
    __shared__ float us[NE];
    int tid = threadIdx.x;
    if (tid < NE) us[tid] = 0.f;
    __syncthreads();

    int warp = tid >> 5, lane = tid & 31;
    int t = blockIdx.x * 4 + warp;

    float acc[NE];
#pragma unroll
    for (int e = 0; e < NE; e++) acc[e] = 0.f;

    const float* xr = x + (size_t)t * DDIM;
    for (int d = lane; d < DDIM; d += 32) {
        float xv = xr[d];
        const float* wr = Wr + d * NE;
#pragma unroll
        for (int e = 0; e < NE; e++) acc[e] += xv * wr[e];
    }
#pragma unroll
    for (int off = 16; off; off >>= 1) {
#pragma unroll
        for (int e = 0; e < NE; e++)
            acc[e] += __shfl_xor_sync(0xffffffffu, acc[e], off);
    }

    if (lane == 0) {
        float m = acc[0];
#pragma unroll
        for (int e = 1; e < NE; e++) m = fmaxf(m, acc[e]);
        float p[NE], s = 0.f;
#pragma unroll
        for (int e = 0; e < NE; e++) { p[e] = __expf(acc[e] - m); s += p[e]; }
        float inv = 1.f / s;
#pragma unroll
        for (int e = 0; e < NE; e++) p[e] *= inv;
#pragma unroll
        for (int e = 0; e < NE; e++) atomicAdd(&us[e], p[e]);

        // top-2, strict > keeps smallest index on ties (matches jax top_k)
        int i0 = 0;
#pragma unroll
        for (int e = 1; e < NE; e++) if (p[e] > p[i0]) i0 = e;
        int i1 = -1;
#pragma unroll
        for (int e = 0; e < NE; e++)
            if (e != i0 && (i1 < 0 || p[e] > p[i1])) i1 = e;

        float denom = 1.f / (p[i0] + p[i1]);
        float w0 = p[i0] * denom;
        float w1 = p[i1] * denom;

        int pos0 = atomicAdd(&g_ecount[i0], 1);
        g_etok[i0][pos0] = t; g_ew[i0][pos0] = w0;
        int pos1 = atomicAdd(&g_ecount[i1], 1);
        g_etok[i1][pos1] = t; g_ew[i1][pos1] = w1;
    }
    __syncthreads();
    if (tid < NE) atomicAdd(&g_usage[tid], (double)us[tid]);
}

// ============================================================
// K2: grouped fused gate/up/expand GEMM + activation epilogue.
// Per expert e: rows = bucketed tokens, A = gathered x rows [count x 1024],
// B = Wg/Wu/Wx [1024 x 1408]. Tile 64x64, BK=16, 4x4 per thread.
// Epilogue: hbuf = combine_w * u * (alpha*silu(g) + (1-alpha)*silu(xp))
// ============================================================
__global__ void __launch_bounds__(256) k_upgate(const float* __restrict__ x,
                                                const float* __restrict__ Wg,
                                                const float* __restrict__ Wu,
                                                const float* __restrict__ Wxp,
                                                const float* __restrict__ alpha) {
    int e = blockIdx.z;
    int count = g_ecount[e];
    int row0 = blockIdx.x * 64;
    if (row0 >= count) return;
    int n0 = blockIdx.y * 64;

    __shared__ float xs[16][65];
    __shared__ float wgs[16][64];
    __shared__ float wus[16][64];
    __shared__ float wxs[16][64];

    int tid = threadIdx.x;
    int tx = tid & 15, ty = tid >> 4;

    float ag[16], au[16], axp[16];
#pragma unroll
    for (int i = 0; i < 16; i++) { ag[i] = 0.f; au[i] = 0.f; axp[i] = 0.f; }

    // X gather-load indexing: 64 rows x 16 cols via float4
    int lr = tid >> 2;          // row in tile 0..63
    int lc = (tid & 3) * 4;     // col 0,4,8,12
    int grow = row0 + lr;
    bool rvalid = grow < count;
    int tok = rvalid ? g_etok[e][grow] : 0;
    const float* xrow = x + (size_t)tok * DDIM;

    // Weight-load indexing: 16 k-rows x 64 cols via float4
    int wr_ = tid >> 4;         // 0..15
    int wc = (tid & 15) * 4;    // 0..60
    size_t wbase = (size_t)e * DDIM * HDIM;
    const float* Wge = Wg + wbase;
    const float* Wue = Wu + wbase;
    const float* Wxe = Wxp + wbase;

    for (int k0 = 0; k0 < DDIM; k0 += 16) {
        float4 xv = rvalid ? *(const float4*)(xrow + k0 + lc)
                           : make_float4(0.f, 0.f, 0.f, 0.f);
        xs[lc + 0][lr] = xv.x;
        xs[lc + 1][lr] = xv.y;
        xs[lc + 2][lr] = xv.z;
        xs[lc + 3][lr] = xv.w;

        size_t woff = (size_t)(k0 + wr_) * HDIM + n0 + wc;
        *(float4*)&wgs[wr_][wc] = *(const float4*)(Wge + woff);
        *(float4*)&wus[wr_][wc] = *(const float4*)(Wue + woff);
        *(float4*)&wxs[wr_][wc] = *(const float4*)(Wxe + woff);
        __syncthreads();

#pragma unroll
        for (int k = 0; k < 16; k++) {
            float xm[4];
#pragma unroll
            for (int i = 0; i < 4; i++) xm[i] = xs[k][ty * 4 + i];
            float4 gv = *(float4*)&wgs[k][tx * 4];
            float4 uv = *(float4*)&wus[k][tx * 4];
            float4 pv = *(float4*)&wxs[k][tx * 4];
#pragma unroll
            for (int i = 0; i < 4; i++) {
                ag[i * 4 + 0] += xm[i] * gv.x;
                ag[i * 4 + 1] += xm[i] * gv.y;
                ag[i * 4 + 2] += xm[i] * gv.z;
                ag[i * 4 + 3] += xm[i] * gv.w;
                au[i * 4 + 0] += xm[i] * uv.x;
                au[i * 4 + 1] += xm[i] * uv.y;
                au[i * 4 + 2] += xm[i] * uv.z;
                au[i * 4 + 3] += xm[i] * uv.w;
                axp[i * 4 + 0] += xm[i] * pv.x;
                axp[i * 4 + 1] += xm[i] * pv.y;
                axp[i * 4 + 2] += xm[i] * pv.z;
                axp[i * 4 + 3] += xm[i] * pv.w;
            }
        }
        __syncthreads();
    }

    float al = alpha[e];
#pragma unroll
    for (int i = 0; i < 4; i++) {
        int grow2 = row0 + ty * 4 + i;
        if (grow2 >= count) continue;
        float w = g_ew[e][grow2];
        float* hrow = &g_hbuf[e][grow2][0];
        float4 outv;
        float vals[4];
#pragma unroll
        for (int j = 0; j < 4; j++) {
            float g  = ag[i * 4 + j];
            float u  = au[i * 4 + j];
            float xp = axp[i * 4 + j];
            float sg = g  * (1.f / (1.f + __expf(-g)));
            float sx = xp * (1.f / (1.f + __expf(-xp)));
            vals[j] = w * u * (al * sg + (1.f - al) * sx);
        }
        outv.x = vals[0]; outv.y = vals[1]; outv.z = vals[2]; outv.w = vals[3];
        *(float4*)(hrow + n0 + tx * 4) = outv;
    }
}

// ============================================================
// K3: grouped down-proj GEMM. A = hbuf[e] [count x 1408], B = Wd[e] [1408 x 1024].
// Epilogue: atomicAdd into out[token].
// ============================================================
__global__ void __launch_bounds__(256) k_down(const float* __restrict__ Wd,
                                              float* __restrict__ out) {
    int e = blockIdx.z;
    int count = g_ecount[e];
    int row0 = blockIdx.x * 64;
    if (row0 >= count) return;
    int n0 = blockIdx.y * 64;

    __shared__ float as_[16][65];
    __shared__ float ws[16][64];

    int tid = threadIdx.x;
    int tx = tid & 15, ty = tid >> 4;

    float c[16];
#pragma unroll
    for (int i = 0; i < 16; i++) c[i] = 0.f;

    int lr = tid >> 2;
    int lc = (tid & 3) * 4;
    int grow = row0 + lr;
    bool rvalid = grow < count;
    const float* arow = rvalid ? &g_hbuf[e][grow][0] : &g_hbuf[e][0][0];

    int wr_ = tid >> 4;
    int wc = (tid & 15) * 4;
    const float* Wde = Wd + (size_t)e * HDIM * DDIM;

    for (int k0 = 0; k0 < HDIM; k0 += 16) {
        float4 av = rvalid ? *(const float4*)(arow + k0 + lc)
                           : make_float4(0.f, 0.f, 0.f, 0.f);
        as_[lc + 0][lr] = av.x;
        as_[lc + 1][lr] = av.y;
        as_[lc + 2][lr] = av.z;
        as_[lc + 3][lr] = av.w;

        *(float4*)&ws[wr_][wc] =
            *(const float4*)(Wde + (size_t)(k0 + wr_) * DDIM + n0 + wc);
        __syncthreads();

#pragma unroll
        for (int k = 0; k < 16; k++) {
            float am[4];
#pragma unroll
            for (int i = 0; i < 4; i++) am[i] = as_[k][ty * 4 + i];
            float4 wv = *(float4*)&ws[k][tx * 4];
#pragma unroll
            for (int i = 0; i < 4; i++) {
                c[i * 4 + 0] += am[i] * wv.x;
                c[i * 4 + 1] += am[i] * wv.y;
                c[i * 4 + 2] += am[i] * wv.z;
                c[i * 4 + 3] += am[i] * wv.w;
            }
        }
        __syncthreads();
    }

#pragma unroll
    for (int i = 0; i < 4; i++) {
        int grow2 = row0 + ty * 4 + i;
        if (grow2 >= count) continue;
        int tok = g_etok[e][grow2];
        float* orow = out + (size_t)tok * DDIM + n0 + tx * 4;
#pragma unroll
        for (int j = 0; j < 4; j++) atomicAdd(&orow[j], c[i * 4 + j]);
    }
}

// ============================================================
// K4: load-balancing loss scalar
// ============================================================
__global__ void k_final(float* __restrict__ out, int out_size) {
    if (threadIdx.x == 0 && blockIdx.x == 0) {
        double s = 0.0;
        for (int e = 0; e < NE; e++) {
            double u = g_usage[e] / (double)TTOK - 1.0 / (double)NE;
            s += u * u;
        }
        float lb = (float)(0.01 * s / (double)NE);
        if (out_size > TTOK * DDIM) out[TTOK * DDIM] = lb;
    }
}

// ============================================================
extern "C" void kernel_launch(void* const* d_in, const int* in_sizes, int n_in,
                              void* d_out, int out_size) {
    const float* x     = (const float*)d_in[0];
    const float* Wr    = (const float*)d_in[1];
    const float* Wg    = (const float*)d_in[2];
    const float* Wu    = (const float*)d_in[3];
    const float* Wxp   = (const float*)d_in[4];
    const float* Wd    = (const float*)d_in[5];
    const float* alpha = (const float*)d_in[6];
    float* out = (float*)d_out;

    // K0: zero out + counters
    k_init<<<(TTOK * DDIM + 255) / 256, 256>>>(out);

    // K1: router + dispatch
    k_router<<<TTOK / 4, 128>>>(x, Wr);

    // K2: fused gate/up/expand grouped GEMM + activation
    dim3 g2(TTOK / 64, HDIM / 64, NE);
    k_upgate<<<g2, 256>>>(x, Wg, Wu, Wxp, alpha);

    // K3: down-proj grouped GEMM + scatter-accumulate
    dim3 g3(TTOK / 64, DDIM / 64, NE);
    k_down<<<g3, 256>>>(Wd, out);

    // K4: lb loss
    k_final<<<1, 32>>>(out, out_size);
}

// round 2
// speedup vs baseline: 1.0002x; 1.0002x over previous
#include <cuda_runtime.h>
#include <math.h>

#define TTOK 8192
#define DDIM 1024
#define HDIM 1408
#define NE   8

// ---- device scratch (static allocations only; no cudaMalloc anywhere) ----
__device__ int    g_ecount[NE];
__device__ int    g_etok[NE][TTOK];
__device__ float  g_ew[NE][TTOK];
__device__ double g_usage[NE];
__device__ float  g_hbuf[NE][TTOK][HDIM];   // ~369 MB static scratch

// ============================================================
// K0: zero output accumulator + counters
// ============================================================
__global__ void k_init(float* __restrict__ out) {
    int i = blockIdx.x * 256 + threadIdx.x;
    if (i < TTOK * DDIM) out[i] = 0.f;
    if (i < NE) { g_ecount[i] = 0; g_usage[i] = 0.0; }
}

// ============================================================
// K1: router — warp per token. logits = x_t . Wr, softmax, top-2,
// scatter into per-expert buckets, usage accumulation (double).
// ============================================================
__global__ void __launch_bounds__(128) k_router(const float* __restrict__ x,
                                                const float* __restrict__ Wr) {
    __shared__ float us[NE];
    int tid = threadIdx.x;
    if (tid < NE) us[tid] = 0.f;
    __syncthreads();

    int warp = tid >> 5, lane = tid & 31;
    int t = blockIdx.x * 4 + warp;

    float acc[NE];
#pragma unroll
    for (int e = 0; e < NE; e++) acc[e] = 0.f;

    const float* xr = x + (size_t)t * DDIM;
    for (int d = lane; d < DDIM; d += 32) {
        float xv = xr[d];
        const float* wr = Wr + d * NE;
#pragma unroll
        for (int e = 0; e < NE; e++) acc[e] += xv * wr[e];
    }
#pragma unroll
    for (int off = 16; off; off >>= 1) {
#pragma unroll
        for (int e = 0; e < NE; e++)
            acc[e] += __shfl_xor_sync(0xffffffffu, acc[e], off);
    }

    if (lane == 0) {
        float m = acc[0];
#pragma unroll
        for (int e = 1; e < NE; e++) m = fmaxf(m, acc[e]);
        float p[NE], s = 0.f;
#pragma unroll
        for (int e = 0; e < NE; e++) { p[e] = __expf(acc[e] - m); s += p[e]; }
        float inv = 1.f / s;
#pragma unroll
        for (int e = 0; e < NE; e++) p[e] *= inv;
#pragma unroll
        for (int e = 0; e < NE; e++) atomicAdd(&us[e], p[e]);

        // top-2, strict > keeps smallest index on ties (matches jax top_k)
        int i0 = 0;
#pragma unroll
        for (int e = 1; e < NE; e++) if (p[e] > p[i0]) i0 = e;
        int i1 = -1;
#pragma unroll
        for (int e = 0; e < NE; e++)
            if (e != i0 && (i1 < 0 || p[e] > p[i1])) i1 = e;

        float denom = 1.f / (p[i0] + p[i1]);
        float w0 = p[i0] * denom;
        float w1 = p[i1] * denom;

        int pos0 = atomicAdd(&g_ecount[i0], 1);
        g_etok[i0][pos0] = t; g_ew[i0][pos0] = w0;
        int pos1 = atomicAdd(&g_ecount[i1], 1);
        g_etok[i1][pos1] = t; g_ew[i1][pos1] = w1;
    }
    __syncthreads();
    if (tid < NE) atomicAdd(&g_usage[tid], (double)us[tid]);
}

// ============================================================
// K2: grouped fused gate/up/expand GEMM + activation epilogue.
// Per expert e: rows = bucketed tokens, A = gathered x rows [count x 1024],
// B = Wg/Wu/Wx [1024 x 1408]. Tile 64x64, BK=16, 4x4 per thread.
// Epilogue: hbuf = combine_w * u * (alpha*silu(g) + (1-alpha)*silu(xp))
// ============================================================
__global__ void __launch_bounds__(256) k_upgate(const float* __restrict__ x,
                                                const float* __restrict__ Wg,
                                                const float* __restrict__ Wu,
                                                const float* __restrict__ Wxp,
                                                const float* __restrict__ alpha) {
    int e = blockIdx.z;
    int count = g_ecount[e];
    int row0 = blockIdx.x * 64;
    if (row0 >= count) return;
    int n0 = blockIdx.y * 64;

    __shared__ float xs[16][65];
    __shared__ float wgs[16][64];
    __shared__ float wus[16][64];
    __shared__ float wxs[16][64];

    int tid = threadIdx.x;
    int tx = tid & 15, ty = tid >> 4;

    float ag[16], au[16], axp[16];
#pragma unroll
    for (int i = 0; i < 16; i++) { ag[i] = 0.f; au[i] = 0.f; axp[i] = 0.f; }

    // X gather-load indexing: 64 rows x 16 cols via float4
    int lr = tid >> 2;          // row in tile 0..63
    int lc = (tid & 3) * 4;     // col 0,4,8,12
    int grow = row0 + lr;
    bool rvalid = grow < count;
    int tok = rvalid ? g_etok[e][grow] : 0;
    const float* xrow = x + (size_t)tok * DDIM;

    // Weight-load indexing: 16 k-rows x 64 cols via float4
    int wr_ = tid >> 4;         // 0..15
    int wc = (tid & 15) * 4;    // 0..60
    size_t wbase = (size_t)e * DDIM * HDIM;
    const float* Wge = Wg + wbase;
    const float* Wue = Wu + wbase;
    const float* Wxe = Wxp + wbase;

    for (int k0 = 0; k0 < DDIM; k0 += 16) {
        float4 xv = rvalid ? *(const float4*)(xrow + k0 + lc)
                           : make_float4(0.f, 0.f, 0.f, 0.f);
        xs[lc + 0][lr] = xv.x;
        xs[lc + 1][lr] = xv.y;
        xs[lc + 2][lr] = xv.z;
        xs[lc + 3][lr] = xv.w;

        size_t woff = (size_t)(k0 + wr_) * HDIM + n0 + wc;
        *(float4*)&wgs[wr_][wc] = *(const float4*)(Wge + woff);
        *(float4*)&wus[wr_][wc] = *(const float4*)(Wue + woff);
        *(float4*)&wxs[wr_][wc] = *(const float4*)(Wxe + woff);
        __syncthreads();

#pragma unroll
        for (int k = 0; k < 16; k++) {
            float xm[4];
#pragma unroll
            for (int i = 0; i < 4; i++) xm[i] = xs[k][ty * 4 + i];
            float4 gv = *(float4*)&wgs[k][tx * 4];
            float4 uv = *(float4*)&wus[k][tx * 4];
            float4 pv = *(float4*)&wxs[k][tx * 4];
#pragma unroll
            for (int i = 0; i < 4; i++) {
                ag[i * 4 + 0] += xm[i] * gv.x;
                ag[i * 4 + 1] += xm[i] * gv.y;
                ag[i * 4 + 2] += xm[i] * gv.z;
                ag[i * 4 + 3] += xm[i] * gv.w;
                au[i * 4 + 0] += xm[i] * uv.x;
                au[i * 4 + 1] += xm[i] * uv.y;
                au[i * 4 + 2] += xm[i] * uv.z;
                au[i * 4 + 3] += xm[i] * uv.w;
                axp[i * 4 + 0] += xm[i] * pv.x;
                axp[i * 4 + 1] += xm[i] * pv.y;
                axp[i * 4 + 2] += xm[i] * pv.z;
                axp[i * 4 + 3] += xm[i] * pv.w;
            }
        }
        __syncthreads();
    }

    float al = alpha[e];
#pragma unroll
    for (int i = 0; i < 4; i++) {
        int grow2 = row0 + ty * 4 + i;
        if (grow2 >= count) continue;
        float w = g_ew[e][grow2];
        float* hrow = &g_hbuf[e][grow2][0];
        float4 outv;
        float vals[4];
#pragma unroll
        for (int j = 0; j < 4; j++) {
            float g  = ag[i * 4 + j];
            float u  = au[i * 4 + j];
            float xp = axp[i * 4 + j];
            float sg = g  * (1.f / (1.f + __expf(-g)));
            float sx = xp * (1.f / (1.f + __expf(-xp)));
            vals[j] = w * u * (al * sg + (1.f - al) * sx);
        }
        outv.x = vals[0]; outv.y = vals[1]; outv.z = vals[2]; outv.w = vals[3];
        *(float4*)(hrow + n0 + tx * 4) = outv;
    }
}

// ============================================================
// K3: grouped down-proj GEMM. A = hbuf[e] [count x 1408], B = Wd[e] [1408 x 1024].
// Epilogue: atomicAdd into out[token].
// ============================================================
__global__ void __launch_bounds__(256) k_down(const float* __restrict__ Wd,
                                              float* __restrict__ out) {
    int e = blockIdx.z;
    int count = g_ecount[e];
    int row0 = blockIdx.x * 64;
    if (row0 >= count) return;
    int n0 = blockIdx.y * 64;

    __shared__ float as_[16][65];
    __shared__ float ws[16][64];

    int tid = threadIdx.x;
    int tx = tid & 15, ty = tid >> 4;

    float c[16];
#pragma unroll
    for (int i = 0; i < 16; i++) c[i] = 0.f;

    int lr = tid >> 2;
    int lc = (tid & 3) * 4;
    int grow = row0 + lr;
    bool rvalid = grow < count;
    const float* arow = rvalid ? &g_hbuf[e][grow][0] : &g_hbuf[e][0][0];

    int wr_ = tid >> 4;
    int wc = (tid & 15) * 4;
    const float* Wde = Wd + (size_t)e * HDIM * DDIM;

    for (int k0 = 0; k0 < HDIM; k0 += 16) {
        float4 av = rvalid ? *(const float4*)(arow + k0 + lc)
                           : make_float4(0.f, 0.f, 0.f, 0.f);
        as_[lc + 0][lr] = av.x;
        as_[lc + 1][lr] = av.y;
        as_[lc + 2][lr] = av.z;
        as_[lc + 3][lr] = av.w;

        *(float4*)&ws[wr_][wc] =
            *(const float4*)(Wde + (size_t)(k0 + wr_) * DDIM + n0 + wc);
        __syncthreads();

#pragma unroll
        for (int k = 0; k < 16; k++) {
            float am[4];
#pragma unroll
            for (int i = 0; i < 4; i++) am[i] = as_[k][ty * 4 + i];
            float4 wv = *(float4*)&ws[k][tx * 4];
#pragma unroll
            for (int i = 0; i < 4; i++) {
                c[i * 4 + 0] += am[i] * wv.x;
                c[i * 4 + 1] += am[i] * wv.y;
                c[i * 4 + 2] += am[i] * wv.z;
                c[i * 4 + 3] += am[i] * wv.w;
            }
        }
        __syncthreads();
    }

#pragma unroll
    for (int i = 0; i < 4; i++) {
        int grow2 = row0 + ty * 4 + i;
        if (grow2 >= count) continue;
        int tok = g_etok[e][grow2];
        float* orow = out + (size_t)tok * DDIM + n0 + tx * 4;
#pragma unroll
        for (int j = 0; j < 4; j++) atomicAdd(&orow[j], c[i * 4 + j]);
    }
}

// ============================================================
// K4: load-balancing loss scalar
// ============================================================
__global__ void k_final(float* __restrict__ out, int out_size) {
    if (threadIdx.x == 0 && blockIdx.x == 0) {
        double s = 0.0;
        for (int e = 0; e < NE; e++) {
            double u = g_usage[e] / (double)TTOK - 1.0 / (double)NE;
            s += u * u;
        }
        float lb = (float)(0.01 * s / (double)NE);
        if (out_size > TTOK * DDIM) out[TTOK * DDIM] = lb;
    }
}

// ============================================================
extern "C" void kernel_launch(void* const* d_in, const int* in_sizes, int n_in,
                              void* d_out, int out_size) {
    const float* x     = (const float*)d_in[0];
    const float* Wr    = (const float*)d_in[1];
    const float* Wg    = (const float*)d_in[2];
    const float* Wu    = (const float*)d_in[3];
    const float* Wxp   = (const float*)d_in[4];
    const float* Wd    = (const float*)d_in[5];
    const float* alpha = (const float*)d_in[6];
    float* out = (float*)d_out;

    // K0: zero out + counters
    k_init<<<(TTOK * DDIM + 255) / 256, 256>>>(out);

    // K1: router + dispatch
    k_router<<<TTOK / 4, 128>>>(x, Wr);

    // K2: fused gate/up/expand grouped GEMM + activation
    dim3 g2(TTOK / 64, HDIM / 64, NE);
    k_upgate<<<g2, 256>>>(x, Wg, Wu, Wxp, alpha);

    // K3: down-proj grouped GEMM + scatter-accumulate
    dim3 g3(TTOK / 64, DDIM / 64, NE);
    k_down<<<g3, 256>>>(Wd, out);

    // K4: lb loss
    k_final<<<1, 32>>>(out, out_size);
}